// round 9
// baseline (speedup 1.0000x reference)
#include <cuda_runtime.h>
#include <cuda_bf16.h>

#define KDIM  64
#define LOG2E 1.4426950408889634f
#define LN2   0.6931471805599453f
#define WPC   4          // warps per CTA; each warp owns TWO rows
#define DIST  4          // emit prefetch distance (steps), power of 2
#define TH    -1000000.0f
#define FULL  0xffffffffu

typedef unsigned long long ull;

__device__ __forceinline__ ull pk2(float a, float b) {
    ull r; asm("mov.b64 %0, {%1, %2};" : "=l"(r) : "f"(a), "f"(b)); return r;
}
__device__ __forceinline__ ull fma2(ull a, ull b, ull c) {
    ull d; asm("fma.rn.f32x2 %0, %1, %2, %3;" : "=l"(d) : "l"(a), "l"(b), "l"(c)); return d;
}
__device__ __forceinline__ ull add2(ull a, ull b) {
    ull d; asm("add.rn.f32x2 %0, %1, %2;" : "=l"(d) : "l"(a), "l"(b)); return d;
}
__device__ __forceinline__ float ex2f(float x) {
    float y; asm("ex2.approx.f32 %0, %1;" : "=f"(y) : "f"(x)); return y;
}
__device__ __forceinline__ float lg2f(float x) {
    float y; asm("lg2.approx.f32 %0, %1;" : "=f"(y) : "f"(x)); return y;
}
__device__ __forceinline__ float scalbn_fast(float x, int d) {
    return __int_as_float(__float_as_int(x) - (d << 23));
}
__device__ __forceinline__ float unpack_add(ull v) {
    float lo, hi; asm("mov.b64 {%0, %1}, %2;" : "=f"(lo), "=f"(hi) : "l"(v));
    return lo + hi;
}

// ONE WARP owns TWO independent batch rows (A, B); lane l owns states (2l, 2l+1)
// of BOTH rows. The two rows' dependency chains interleave in the scheduler (pure
// ILP, zero extra sync). Ec = exp(trans) register matrix is shared between rows.
// Exp-domain recursion per row (no per-step lg2/ex2):
//   e_j(t) = [ m_t ? (sum_i e_i(t-1) E[i][j]) * 2^(emit_j lg2e) : e_j(t-1) ] * 2^(-d)
// d = exponent-field of e_0(t-1), read directly from sh_e[..][0] (no sh_di, no
// lane-0 branch); C2i += d exactly. alpha2_j = C2i + lg2(e_j). Steps t >= N run
// masked (m=0): pure frame shift, result invariant.
__global__ __launch_bounds__(32 * WPC, 1) void crf_fwd_kernel(
    const float* __restrict__ y_pred,   // [B, N, K]
    const float* __restrict__ trans,    // [K, K]
    const int*   __restrict__ y_true,   // [B, N]
    float*       __restrict__ out,      // [B]
    int N, int B)
{
    __shared__ float sh_trans[KDIM * KDIM];
    __shared__ __align__(16) float sh_e[WPC][2][2][KDIM];  // [warp][row][buf][state]

    const int tid  = threadIdx.x;
    const int lane = tid & 31;
    const int w    = tid >> 5;
    const int pr   = blockIdx.x * WPC + w;   // row-pair index
    const int rowA = pr * 2;

    for (int i = tid; i < KDIM * KDIM; i += 32 * WPC) sh_trans[i] = trans[i];
    __syncthreads();
    if (rowA >= B) return;
    const bool hasB = (rowA + 1) < B;
    const int rowB = hasB ? rowA + 1 : rowA;

    const int sa = 2 * lane, sb = sa + 1;

    // Shared E columns (row-independent): Ec*[k] packs trans rows (2k, 2k+1).
    ull Eca[KDIM / 2], Ecb[KDIM / 2];
#pragma unroll
    for (int k = 0; k < KDIM / 2; ++k) {
        Eca[k] = pk2(__expf(sh_trans[(2 * k) * KDIM + sa]),
                     __expf(sh_trans[(2 * k + 1) * KDIM + sa]));
        Ecb[k] = pk2(__expf(sh_trans[(2 * k) * KDIM + sb]),
                     __expf(sh_trans[(2 * k + 1) * KDIM + sb]));
    }

    const float* yA = y_pred + (size_t)rowA * N * KDIM;
    const int*   tA = y_true + (size_t)rowA * N;
    const float* yB = y_pred + (size_t)rowB * N * KDIM;
    const int*   tB = y_true + (size_t)rowB * N;

    // ---- t = 0, both rows ----
    float2 y0A = *(const float2*)(yA + sa);
    float2 y0B = *(const float2*)(yB + sa);
    int yt0A = tA[0], yt0B = tB[0];
    unsigned m0A = __all_sync(FULL, (y0A.x > TH) && (y0A.y > TH));
    unsigned m0B = __all_sync(FULL, (y0B.x > TH) && (y0B.y > TH));
    float fm0A = m0A ? 1.0f : 0.0f, fm0B = m0B ? 1.0f : 0.0f;
    float eaA = ex2f((y0A.x * fm0A) * LOG2E), ebA = ex2f((y0A.y * fm0A) * LOG2E);
    float eaB = ex2f((y0B.x * fm0B) * LOG2E), ebB = ex2f((y0B.y * fm0B) * LOG2E);
    float pointA = ((sa == yt0A) ? y0A.x * fm0A : 0.0f) + ((sb == yt0A) ? y0A.y * fm0A : 0.0f);
    float pointB = ((sa == yt0B) ? y0B.x * fm0B : 0.0f) + ((sb == yt0B) ? y0B.y * fm0B : 0.0f);
    int   C2iA = 0, C2iB = 0;
    float tvA = 0.0f, tvB = 0.0f;
    *(float2*)&sh_e[w][0][0][sa] = make_float2(eaA, ebA);
    *(float2*)&sh_e[w][1][0][sa] = make_float2(eaB, ebB);
    float fmprevA = fm0A, fmprevB = fm0B;

    // ---- prime prefetch rings ----
    float2 ringA[DIST], ringB[DIST];
#pragma unroll
    for (int p = 1; p <= DIST; ++p) {
        int tt = (p < N) ? p : (N - 1);
        ringA[p & (DIST - 1)] = *(const float2*)(yA + (size_t)tt * KDIM + sa);
        ringB[p & (DIST - 1)] = *(const float2*)(yB + (size_t)tt * KDIM + sa);
    }
    int ytcA = tA[(1 < N) ? 1 : (N - 1)], ytnA = tA[(2 < N) ? 2 : (N - 1)];
    int ytcB = tB[(1 < N) ? 1 : (N - 1)], ytnB = tB[(2 < N) ? 2 : (N - 1)];
    float trvA = sh_trans[yt0A * KDIM + ytcA];
    float trvB = sh_trans[yt0B * KDIM + ytcB];
    unsigned mcA = __all_sync(FULL, (ringA[1 & (DIST - 1)].x > TH) && (ringA[1 & (DIST - 1)].y > TH));
    unsigned mcB = __all_sync(FULL, (ringB[1 & (DIST - 1)].x > TH) && (ringB[1 & (DIST - 1)].y > TH));
    if (1 >= N) { mcA = 0u; mcB = 0u; }
    float fmcA = mcA ? 1.0f : 0.0f, fmcB = mcB ? 1.0f : 0.0f;

#define STEP(T, RP, RPN, BUF, PBUF)                                                  \
    {                                                                                \
        float2 yvA = ringA[RP];                                                      \
        float2 yvB = ringB[RP];                                                      \
        int tt = ((T) + DIST < N) ? ((T) + DIST) : (N - 1);                          \
        ringA[RP] = *(const float2*)(yA + (size_t)tt * KDIM + sa);                   \
        ringB[RP] = *(const float2*)(yB + (size_t)tt * KDIM + sa);                   \
        unsigned mnA = __all_sync(FULL, (ringA[RPN].x > TH) && (ringA[RPN].y > TH)); \
        unsigned mnB = __all_sync(FULL, (ringB[RPN].x > TH) && (ringB[RPN].y > TH)); \
        mnA = ((T) + 1 < N) ? mnA : 0u;                                              \
        mnB = ((T) + 1 < N) ? mnB : 0u;                                              \
        int tn = ((T) + 2 < N) ? ((T) + 2) : (N - 1);                                \
        int ytn2A = tA[tn], ytn2B = tB[tn];                                          \
        float trvnA = sh_trans[ytcA * KDIM + ytnA];                                  \
        float trvnB = sh_trans[ytcB * KDIM + ytnB];                                  \
        float flA = fmcA * LOG2E, flB = fmcB * LOG2E;                                \
        float paA = ex2f(yvA.x * flA), pbA = ex2f(yvA.y * flA);                      \
        float paB = ex2f(yvB.x * flB), pbB = ex2f(yvB.y * flB);                      \
        __syncwarp();                                                                \
        int dA = (int)((unsigned)__float_as_int(sh_e[w][0][PBUF][0]) >> 23) - 127;   \
        int dB = (int)((unsigned)__float_as_int(sh_e[w][1][PBUF][0]) >> 23) - 127;   \
        ull Aa0 = 0, Aa1 = 0, Ab0 = 0, Ab1 = 0;                                      \
        ull Ba0 = 0, Ba1 = 0, Bb0 = 0, Bb1 = 0;                                      \
        const ulonglong2* epA = (const ulonglong2*)sh_e[w][0][PBUF];                 \
        const ulonglong2* epB = (const ulonglong2*)sh_e[w][1][PBUF];                 \
        _Pragma("unroll")                                                            \
        for (int k = 0; k < KDIM / 4; ++k) {                                         \
            ulonglong2 eA = epA[k];                                                  \
            ulonglong2 eB = epB[k];                                                  \
            Aa0 = fma2(eA.x, Eca[2 * k], Aa0); Aa1 = fma2(eA.y, Eca[2 * k + 1], Aa1);\
            Ab0 = fma2(eA.x, Ecb[2 * k], Ab0); Ab1 = fma2(eA.y, Ecb[2 * k + 1], Ab1);\
            Ba0 = fma2(eB.x, Eca[2 * k], Ba0); Ba1 = fma2(eB.y, Eca[2 * k + 1], Ba1);\
            Bb0 = fma2(eB.x, Ecb[2 * k], Bb0); Bb1 = fma2(eB.y, Ecb[2 * k + 1], Bb1);\
        }                                                                            \
        float sAa = unpack_add(add2(Aa0, Aa1));                                      \
        float sAb = unpack_add(add2(Ab0, Ab1));                                      \
        float sBa = unpack_add(add2(Ba0, Ba1));                                      \
        float sBb = unpack_add(add2(Bb0, Bb1));                                      \
        float qAa = mcA ? sAa * paA : eaA;                                           \
        float qAb = mcA ? sAb * pbA : ebA;                                           \
        float qBa = mcB ? sBa * paB : eaB;                                           \
        float qBb = mcB ? sBb * pbB : ebB;                                           \
        eaA = scalbn_fast(qAa, dA); ebA = scalbn_fast(qAb, dA);                      \
        eaB = scalbn_fast(qBa, dB); ebB = scalbn_fast(qBb, dB);                      \
        C2iA += dA; C2iB += dB;                                                      \
        pointA += ((sa == ytcA) ? yvA.x * fmcA : 0.0f)                               \
                + ((sb == ytcA) ? yvA.y * fmcA : 0.0f);                              \
        pointB += ((sa == ytcB) ? yvB.x * fmcB : 0.0f)                               \
                + ((sb == ytcB) ? yvB.y * fmcB : 0.0f);                              \
        tvA += trvA * (fmprevA * fmcA);                                              \
        tvB += trvB * (fmprevB * fmcB);                                              \
        *(float2*)&sh_e[w][0][BUF][sa] = make_float2(eaA, ebA);                      \
        *(float2*)&sh_e[w][1][BUF][sa] = make_float2(eaB, ebB);                      \
        fmprevA = fmcA; fmprevB = fmcB;                                              \
        mcA = mnA; fmcA = mnA ? 1.0f : 0.0f;                                         \
        mcB = mnB; fmcB = mnB ? 1.0f : 0.0f;                                         \
        trvA = trvnA; ytcA = ytnA; ytnA = ytn2A;                                     \
        trvB = trvnB; ytcB = ytnB; ytnB = ytn2B;                                     \
    }

    // ---- main loop: t0 === 1 (mod 4); overflow steps are harmless dummy steps ----
    for (int t0 = 1; t0 < N; t0 += 4) {
        STEP(t0 + 0, 1, 2, 1, 0)
        STEP(t0 + 1, 2, 3, 0, 1)
        STEP(t0 + 2, 3, 0, 1, 0)
        STEP(t0 + 3, 0, 1, 0, 1)
    }
#undef STEP

    // ---- epilogue: per-row warp reductions ----
    float seA = eaA + ebA, ppA = pointA;
    float seB = eaB + ebB, ppB = pointB;
#pragma unroll
    for (int o = 16; o > 0; o >>= 1) {
        seA += __shfl_xor_sync(FULL, seA, o);
        ppA += __shfl_xor_sync(FULL, ppA, o);
        seB += __shfl_xor_sync(FULL, seB, o);
        ppB += __shfl_xor_sync(FULL, ppB, o);
    }
    if (lane == 0) {
        out[rowA] = LN2 * ((float)C2iA + lg2f(seA)) - (ppA + tvA);
        if (hasB) out[rowB] = LN2 * ((float)C2iB + lg2f(seB)) - (ppB + tvB);
    }
}

extern "C" void kernel_launch(void* const* d_in, const int* in_sizes, int n_in,
                              void* d_out, int out_size) {
    const float* y_pred = (const float*)d_in[0];   // [B, N, K] f32
    const float* trans  = (const float*)d_in[1];   // [K, K]    f32
    const int*   y_true = (const int*)  d_in[2];   // [B, N]    i32
    float* out = (float*)d_out;                    // [B]       f32

    int B = out_size;                  // 512
    int N = in_sizes[2] / B;           // 1024
    int pairs = (B + 1) / 2;           // 256 row-pairs
    int blocks = (pairs + WPC - 1) / WPC;   // 64
    crf_fwd_kernel<<<blocks, 32 * WPC>>>(y_pred, trans, y_true, out, N, B);
}

// round 10
// speedup vs baseline: 1.5172x; 1.5172x over previous
#include <cuda_runtime.h>
#include <cuda_bf16.h>

#define KDIM  64
#define LOG2E 1.4426950408889634f
#define LN2   0.6931471805599453f
#define DIST  4          // emit prefetch distance (steps), power of 2
#define TH    -1000000.0f
#define FULL  0xffffffffu

typedef unsigned long long ull;

__device__ __forceinline__ ull pk2(float a, float b) {
    ull r; asm("mov.b64 %0, {%1, %2};" : "=l"(r) : "f"(a), "f"(b)); return r;
}
__device__ __forceinline__ ull fma2(ull a, ull b, ull c) {
    ull d; asm("fma.rn.f32x2 %0, %1, %2, %3;" : "=l"(d) : "l"(a), "l"(b), "l"(c)); return d;
}
__device__ __forceinline__ ull add2(ull a, ull b) {
    ull d; asm("add.rn.f32x2 %0, %1, %2;" : "=l"(d) : "l"(a), "l"(b)); return d;
}
__device__ __forceinline__ float ex2f(float x) {
    float y; asm("ex2.approx.f32 %0, %1;" : "=f"(y) : "f"(x)); return y;
}
__device__ __forceinline__ float lg2f(float x) {
    float y; asm("lg2.approx.f32 %0, %1;" : "=f"(y) : "f"(x)); return y;
}
__device__ __forceinline__ float scalbn_fast(float x, int d) {
    return __int_as_float(__float_as_int(x) - (d << 23));
}
__device__ __forceinline__ float unpack_add(ull v) {
    float lo, hi; asm("mov.b64 {%0, %1}, %2;" : "=f"(lo), "=f"(hi) : "l"(v));
    return lo + hi;
}

// CTA = 128 threads = 2 rows x 2 warps. Each lane owns ONE state (st = h*32+lane).
// Exp-domain recursion (no per-step lg2/ex2):
//   e_j(t) = [ m_t ? (sum_i e_i(t-1) E[i][j]) * 2^(emit_j lg2e) : e_j(t-1) ] * 2^(-d)
// d = exponent-field of e_0(t-1) (read from sh_e, no broadcast var, exact integer
// accumulation in C2i). Per-step sync = ONE plain __syncthreads (BAR floor ~7cyc).
// Mask votes: per-warp __all_sync into a 4-deep slot ring (slot = t & 3), written
// one step ahead pre-barrier, read one step ahead post-barrier -> every aliasing
// write/read pair is separated by >= 1 barrier. tv/point computed warp-uniformly
// (no lane-0 branches). E built from GLOBAL trans (no sh_trans). Steps t >= N run
// masked (m = 0): pure frame shift, result invariant.
__global__ __launch_bounds__(128, 1) void crf_fwd_kernel(
    const float* __restrict__ y_pred,   // [B, N, K]
    const float* __restrict__ trans,    // [K, K]
    const int*   __restrict__ y_true,   // [B, N]
    float*       __restrict__ out,      // [B]
    int N, int B)
{
    __shared__ __align__(16) float sh_e[2][2][KDIM];   // [row-in-CTA][buf][state]
    __shared__ unsigned sh_mv[4][2][2];                // [slot][row][warp-half]
    __shared__ float sh_red[2][2][2];                  // [row][half][{se, point}]

    const int tid  = threadIdx.x;
    const int lane = tid & 31;
    const int wid  = tid >> 5;
    const int r    = wid >> 1;                  // row within CTA (0/1)
    const int h    = wid & 1;                   // state half (0/1)
    int row = blockIdx.x * 2 + r;
    if (row >= B) row = B - 1;                  // clamp (dup row writes same value)
    const int st = h * 32 + lane;               // my state

    // My E column from GLOBAL: Ec[k] packs trans rows (2k, 2k+1), col st.
    ull Ec[KDIM / 2];
#pragma unroll
    for (int k = 0; k < KDIM / 2; ++k) {
        Ec[k] = pk2(__expf(trans[(2 * k) * KDIM + st]),
                    __expf(trans[(2 * k + 1) * KDIM + st]));
    }

    const float* yrow = y_pred + (size_t)row * N * KDIM;
    const int*   trow = y_true + (size_t)row * N;

    // ---- t = 0 ----
    float y0 = yrow[st];
    int yt0 = trow[0];
    sh_mv[0][r][h] = __all_sync(FULL, y0 > TH);

    // prime emit ring (steps 1..DIST)
    float ring[DIST];
#pragma unroll
    for (int p = 1; p <= DIST; ++p) {
        int tt = (p < N) ? p : (N - 1);
        ring[p & (DIST - 1)] = yrow[(size_t)tt * KDIM + st];
    }
    {   // vote for step 1 into slot 1
        unsigned v1 = __all_sync(FULL, ring[1 & (DIST - 1)] > TH);
        sh_mv[1][r][h] = (1 < N) ? v1 : 0u;
    }
    __syncthreads();                            // publishes slots 0, 1

    unsigned m0 = sh_mv[0][r][0] & sh_mv[0][r][1];
    float fm0 = m0 ? 1.0f : 0.0f;
    float e = ex2f((y0 * fm0) * LOG2E);
    float point = (st == yt0) ? y0 * fm0 : 0.0f;
    int   C2i = 0;
    float tv = 0.0f;
    sh_e[r][0][st] = e;
    float fmprev = fm0;
    unsigned mcur = sh_mv[1][r][0] & sh_mv[1][r][1];
    float fmcur = mcur ? 1.0f : 0.0f;

    // tv / label pipeline (warp-uniform; LDGs L1-resident after warmup)
    int yt_cur = trow[(1 < N) ? 1 : (N - 1)];
    int yt_nx  = trow[(2 < N) ? 2 : (N - 1)];
    float trv_cur = trans[yt0 * KDIM + yt_cur];
    __syncthreads();                            // t=0 e-stores visible

    // slots: MSN = (T+1) & 3 written pre-bar; mnext read post-bar from MSN.
#define STEP(T, RP, RPN, BUF, PBUF, MSN)                                             \
    {                                                                                \
        float yv = ring[RP];                                                         \
        int tt = ((T) + DIST < N) ? ((T) + DIST) : (N - 1);                          \
        ring[RP] = yrow[(size_t)tt * KDIM + st];                                     \
        unsigned vn = __all_sync(FULL, ring[RPN] > TH);                              \
        sh_mv[MSN][r][h] = ((T) + 1 < N) ? vn : 0u;   /* vote for step T+1 */        \
        int tn = ((T) + 2 < N) ? ((T) + 2) : (N - 1);                                \
        int yt_nx2 = trow[tn];                                                       \
        float trv_next = trans[yt_cur * KDIM + yt_nx];                               \
        float p = ex2f(yv * (fmcur * LOG2E));   /* MUFU pre-barrier */               \
        __syncthreads();        /* publishes e(t-1) + slot (T+1) votes */            \
        unsigned mnext = sh_mv[MSN][r][0] & sh_mv[MSN][r][1];                        \
        int d = (int)((unsigned)__float_as_int(sh_e[r][PBUF][0]) >> 23) - 127;       \
        ull A0 = 0, A1 = 0, A2 = 0, A3 = 0;                                          \
        const ulonglong2* ep = (const ulonglong2*)sh_e[r][PBUF];                     \
        _Pragma("unroll")                                                            \
        for (int k = 0; k < KDIM / 4; ++k) {                                         \
            ulonglong2 ee = ep[k];                                                   \
            if (k & 1) { A2 = fma2(ee.x, Ec[2 * k], A2);                             \
                         A3 = fma2(ee.y, Ec[2 * k + 1], A3); }                       \
            else       { A0 = fma2(ee.x, Ec[2 * k], A0);                             \
                         A1 = fma2(ee.y, Ec[2 * k + 1], A1); }                       \
        }                                                                            \
        float s = unpack_add(add2(add2(A0, A1), add2(A2, A3)));                      \
        float q = mcur ? s * p : e;                                                  \
        e = scalbn_fast(q, d);                                                       \
        C2i += d;                                                                    \
        point += (st == yt_cur) ? yv * fmcur : 0.0f;                                 \
        tv += trv_cur * (fmprev * fmcur);                                            \
        sh_e[r][BUF][st] = e;                                                        \
        fmprev = fmcur;                                                              \
        mcur = mnext; fmcur = mnext ? 1.0f : 0.0f;                                   \
        trv_cur = trv_next; yt_cur = yt_nx; yt_nx = yt_nx2;                          \
    }

    // ---- main loop: t0 === 1 (mod 4); overflow steps run masked (harmless) ----
    for (int t0 = 1; t0 < N; t0 += 4) {
        STEP(t0 + 0, 1, 2, 1, 0, 2)
        STEP(t0 + 1, 2, 3, 0, 1, 3)
        STEP(t0 + 2, 3, 0, 1, 0, 0)
        STEP(t0 + 3, 0, 1, 0, 1, 1)
    }
#undef STEP

    // ---- epilogue: reduce 2^(w) and point over the row's 64 states ----
    float se = e, pp = point;
#pragma unroll
    for (int o = 16; o > 0; o >>= 1) {
        se += __shfl_xor_sync(FULL, se, o);
        pp += __shfl_xor_sync(FULL, pp, o);
    }
    if (lane == 0) { sh_red[r][h][0] = se; sh_red[r][h][1] = pp; }
    __syncthreads();
    if (h == 0 && lane == 0) {
        float seT = sh_red[r][0][0] + sh_red[r][1][0];
        float ppT = sh_red[r][0][1] + sh_red[r][1][1];
        out[row] = LN2 * ((float)C2i + lg2f(seT)) - (ppT + tv);
    }
}

extern "C" void kernel_launch(void* const* d_in, const int* in_sizes, int n_in,
                              void* d_out, int out_size) {
    const float* y_pred = (const float*)d_in[0];   // [B, N, K] f32
    const float* trans  = (const float*)d_in[1];   // [K, K]    f32
    const int*   y_true = (const int*)  d_in[2];   // [B, N]    i32
    float* out = (float*)d_out;                    // [B]       f32

    int B = out_size;                  // 512
    int N = in_sizes[2] / B;           // 1024
    int blocks = (B + 1) / 2;          // 256 CTAs, 2 rows each
    crf_fwd_kernel<<<blocks, 128>>>(y_pred, trans, y_true, out, N, B);
}